// round 7
// baseline (speedup 1.0000x reference)
#include <cuda_runtime.h>
#include <cstdint>

// OneDilate: out = depthwise 10x10 box filter over (1-x)*0.5 with replicate pad 4.
// x: [32,3,512,512] f32, out: [32,3,511,511] f32.
// Separable sliding-window box filter, one fused kernel, smem tiling.

#define IN_H   512
#define IN_W   512
#define OUT_H  511
#define OUT_W  511
#define PLANES 96          // 32*3
#define TILE_X 128
#define TILE_Y 64
#define A_H    73          // TILE_Y + 9
#define A_W    137         // TILE_X + 9
#define H_STR  129         // padded stride for H buffer (bank-conflict-free)
#define NTHREADS 256

__global__ __launch_bounds__(NTHREADS, 2)
void onedilate_kernel(const float* __restrict__ x, float* __restrict__ out)
{
    extern __shared__ float sm[];
    float* A  = sm;                 // A_H * A_W   (haloed, scaled input tile)
    float* Hs = sm + A_H * A_W;     // A_H * H_STR (horizontal 10-sums)

    const int tx0 = blockIdx.x * TILE_X;
    const int ty0 = blockIdx.y * TILE_Y;
    const int p   = blockIdx.z;
    const float* __restrict__ xp = x   + (size_t)p * IN_H * IN_W;
    float* __restrict__       op = out + (size_t)p * OUT_H * OUT_W;
    const int tid = threadIdx.x;

    // -------- Phase 1: load haloed tile, apply (1-x)*0.5, clamp (replicate pad)
    #pragma unroll 4
    for (int idx = tid; idx < A_H * A_W; idx += NTHREADS) {
        int r = idx / A_W;
        int c = idx - r * A_W;
        int g = ty0 + r - 4;
        g = (g < 0) ? 0 : (g > IN_H - 1 ? IN_H - 1 : g);
        int b = tx0 + c - 4;
        b = (b < 0) ? 0 : (b > IN_W - 1 ? IN_W - 1 : b);
        A[idx] = (1.0f - xp[g * IN_W + b]) * 0.5f;
    }
    __syncthreads();

    // -------- Phase 2: horizontal sliding 10-sum.
    // item -> (r = item % 73, chunk = item / 73); consecutive lanes hit
    // consecutive rows (addr stride 137 -> bank stride 9, conflict-free).
    for (int item = tid; item < A_H * 4; item += NTHREADS) {
        int r     = item % A_H;
        int chunk = item / A_H;
        int c0    = chunk * 32;
        const float* Ar = A + r * A_W;
        float* Hr = Hs + r * H_STR;
        float s = 0.0f;
        #pragma unroll
        for (int k = 0; k < 10; k++) s += Ar[c0 + k];
        Hr[c0] = s;
        #pragma unroll 4
        for (int j = 1; j < 32; j++) {
            s += Ar[c0 + j + 9] - Ar[c0 + j - 1];
            Hr[c0 + j] = s;
        }
    }
    __syncthreads();

    // -------- Phase 3: vertical sliding 10-sum, store coalesced.
    {
        const int xc = tid & (TILE_X - 1);     // column within tile
        const int y0 = (tid >> 7) * 32;        // row strip: 0 or 32
        const int ox = tx0 + xc;
        const bool xv = (ox < OUT_W);

        float s = 0.0f;
        #pragma unroll
        for (int k = 0; k < 10; k++) s += Hs[(y0 + k) * H_STR + xc];

        int oy = ty0 + y0;
        if (xv && oy < OUT_H) op[(size_t)oy * OUT_W + ox] = s;
        #pragma unroll 4
        for (int j = 1; j < 32; j++) {
            s += Hs[(y0 + j + 9) * H_STR + xc] - Hs[(y0 + j - 1) * H_STR + xc];
            oy = ty0 + y0 + j;
            if (xv && oy < OUT_H) op[(size_t)oy * OUT_W + ox] = s;
        }
    }
}

extern "C" void kernel_launch(void* const* d_in, const int* in_sizes, int n_in,
                              void* d_out, int out_size)
{
    const float* x = (const float*)d_in[0];
    float* out = (float*)d_out;

    const int smem = (A_H * A_W + A_H * H_STR) * (int)sizeof(float);  // 77,672 B
    static bool attr_set = false;
    // cudaFuncSetAttribute is a host-side, non-stream call: capture-safe.
    // Call unconditionally to stay stateless-deterministic; it is idempotent.
    cudaFuncSetAttribute(onedilate_kernel,
                         cudaFuncAttributeMaxDynamicSharedMemorySize, smem);
    (void)attr_set;

    dim3 grid((OUT_W + TILE_X - 1) / TILE_X,   // 4
              (OUT_H + TILE_Y - 1) / TILE_Y,   // 8
              PLANES);                          // 96
    onedilate_kernel<<<grid, NTHREADS, smem>>>(x, out);
}

// round 9
// speedup vs baseline: 1.9883x; 1.9883x over previous
#include <cuda_runtime.h>
#include <cstdint>

// OneDilate: out = depthwise 10x10 box filter over (1-x)*0.5 with replicate pad 4.
// x: [32,3,512,512] f32 -> out: [32,3,511,511] f32.
//
// Vertical-first separable box filter:
//   - thread-per-column vertical sliding 10-sum of RAW x (top re-read hits L1)
//   - 16-row V chunks in 8.96 KB smem (high occupancy: ~60 warps/SM)
//   - horizontal 10-sum via 4x LDS.128 per thread (4 outputs), conflict-free
//   - out = 50 - 0.5 * (sum of 100 raw taps)   since f = (1-x)*0.5

#define IN_H   512
#define IN_W   512
#define OUT_H  511
#define OUT_W  511
#define PLANES 96

#define TILE_X 128
#define TILE_Y 128
#define VW     137          // columns in V = TILE_X + 9
#define VSTR   140          // padded stride (16B-aligned rows, conflict-free)
#define CH     16           // rows per chunk
#define NCHUNK 8            // TILE_Y / CH
#define NT     160          // 5 warps: 137 vertical cols / 32 per-row horiz

__global__ __launch_bounds__(NT)
void onedilate_kernel(const float* __restrict__ x, float* __restrict__ out)
{
    __shared__ __align__(16) float V[CH * VSTR];   // 8960 B

    const int tx0 = blockIdx.x * TILE_X;
    const int ty0 = blockIdx.y * TILE_Y;
    const int p   = blockIdx.z;
    const float* __restrict__ xp = x   + (size_t)p * IN_H * IN_W;
    float* __restrict__       op = out + (size_t)p * OUT_H * OUT_W;
    const int t = threadIdx.x;

    // ---- vertical role: one input column per thread (clamped = replicate pad)
    int col = tx0 - 4 + t;
    col = (col < 0) ? 0 : (col > IN_W - 1 ? IN_W - 1 : col);
    const float* __restrict__ xc = xp + col;

    // warm-up: raw sum of rows [ty0-4 .. ty0+4] (clamped)
    float s = 0.0f;
    if (t < VW) {
        #pragma unroll
        for (int k = 0; k < 9; k++) {
            int g = ty0 - 4 + k;
            g = (g < 0) ? 0 : (g > IN_H - 1 ? IN_H - 1 : g);
            s += xc[g * IN_W];
        }
    }

    for (int ck = 0; ck < NCHUNK; ck++) {
        const int jbase = ty0 + ck * CH;

        // ---- vertical sliding: emit CH rows of V (raw 10-row column sums)
        if (t < VW) {
            #pragma unroll
            for (int jj = 0; jj < CH; jj++) {
                int bot = jbase + jj + 5;               // bottom of window oy+5
                bot = (bot > IN_H - 1) ? IN_H - 1 : bot;
                int top = jbase + jj - 4;               // top of window oy-4
                top = (top < 0) ? 0 : top;
                s += xc[bot * IN_W];
                V[jj * VSTR + t] = s;
                s -= xc[top * IN_W];                    // L1-hot (read 9 rows ago)
            }
        }
        __syncthreads();

        // ---- horizontal: warp-per-row, 4 outputs per thread via 4x LDS.128
        for (int item = t; item < CH * 32; item += NT) {
            const int jj = item >> 5;          // V row
            const int l  = item & 31;          // 4-col group within row
            const float4* __restrict__ Vv =
                (const float4*)(V + jj * VSTR + 4 * l);
            float4 a = Vv[0], b = Vv[1], c4 = Vv[2], d = Vv[3];

            float s0 = ((a.x + a.y) + (a.z + a.w))
                     + ((b.x + b.y) + (b.z + b.w))
                     + (c4.x + c4.y);
            float s1 = s0 - a.x + c4.z;
            float s2 = s1 - a.y + c4.w;
            float s3 = s2 - a.z + d.x;

            const int oy = jbase + jj;
            const int ox = tx0 + 4 * l;
            if (oy < OUT_H) {
                float* __restrict__ o = op + (size_t)oy * OUT_W + ox;
                if (ox + 3 < OUT_W) {
                    o[0] = fmaf(s0, -0.5f, 50.0f);
                    o[1] = fmaf(s1, -0.5f, 50.0f);
                    o[2] = fmaf(s2, -0.5f, 50.0f);
                    o[3] = fmaf(s3, -0.5f, 50.0f);
                } else {
                    if (ox + 0 < OUT_W) o[0] = fmaf(s0, -0.5f, 50.0f);
                    if (ox + 1 < OUT_W) o[1] = fmaf(s1, -0.5f, 50.0f);
                    if (ox + 2 < OUT_W) o[2] = fmaf(s2, -0.5f, 50.0f);
                }
            }
        }
        __syncthreads();
    }
}

extern "C" void kernel_launch(void* const* d_in, const int* in_sizes, int n_in,
                              void* d_out, int out_size)
{
    const float* x = (const float*)d_in[0];
    float* out = (float*)d_out;

    dim3 grid((OUT_W + TILE_X - 1) / TILE_X,   // 4
              (OUT_H + TILE_Y - 1) / TILE_Y,   // 4
              PLANES);                          // 96  -> 1536 CTAs
    onedilate_kernel<<<grid, NT>>>(x, out);
}